// round 8
// baseline (speedup 1.0000x reference)
#include <cuda_runtime.h>
#include <cuda_fp16.h>

// DifferentiableKendallTau: tau = sum_{i<j} tanh((p_j-p_i)*(t_j-t_i)/0.1) / (n*(n-1)/2)
// n = 8192. Single kernel, tiled all-pairs.
// Key trick: tanh.approx.f16x2 evaluates TWO pair agreements per MUFU slot,
// halving the MUFU roofline vs f32 tanh. Arguments stay fp32 (add/mul.rn.f32x2),
// only the tanh itself is fp16; accumulation is fp32 -> double.

#define TILE 256
typedef unsigned long long ull;

__device__ double       g_tau_sum;   // zero at module load; last block resets each launch
__device__ unsigned int g_count;

__device__ __forceinline__ float fast_tanhf(float x) {
    float y; asm("tanh.approx.f32 %0, %1;" : "=f"(y) : "f"(x)); return y;
}

__device__ __forceinline__ ull packf2(float x, float y) {
    float2 f = make_float2(x, y);
    return *reinterpret_cast<ull*>(&f);
}

// Two pair-arguments -> one f16x2 register.
// a = {10*p_i0, 10*p_i1}, b = {t_i0, t_i1}, npj2 = {-10*pj, -10*pj}, ntj2 = {-tj, -tj}
// x_k = (p_ik - pj)*10 * (t_ik - tj)  == 10*pd*td (sign-symmetric, matches reference)
__device__ __forceinline__ unsigned pair_args_h2(ull a, ull b, ull npj2, ull ntj2) {
    unsigned r;
    asm("{\n\t"
        ".reg .b64 pd, td, x2;\n\t"
        ".reg .f32 xlo, xhi;\n\t"
        "add.rn.f32x2 pd, %1, %2;\n\t"
        "add.rn.f32x2 td, %3, %4;\n\t"
        "mul.rn.f32x2 x2, pd, td;\n\t"
        "mov.b64 {xlo, xhi}, x2;\n\t"
        "cvt.rn.f16x2.f32 %0, xhi, xlo;\n\t"
        "}" : "=r"(r) : "l"(a), "l"(npj2), "l"(b), "l"(ntj2));
    return r;
}

__device__ __forceinline__ unsigned tanh_h2(unsigned x) {
    unsigned y; asm("tanh.approx.f16x2 %0, %1;" : "=r"(y) : "r"(x)); return y;
}

__global__ void __launch_bounds__(TILE)
ktau_kernel(const float* __restrict__ pred,
            const float* __restrict__ target,
            int nt, float* __restrict__ out, double inv_pairs) {
    // Decode linear block id -> (bi, bj), bi <= bj (upper-triangular tile pairs).
    int b = blockIdx.x;
    int bi = 0;
    int rem = b;
    while (rem >= nt - bi) { rem -= nt - bi; bi++; }
    int bj = bi + rem;

    __shared__ ull spp[TILE / 2];   // packed {10*p_{2k}, 10*p_{2k+1}}
    __shared__ ull stt[TILE / 2];   // packed {t_{2k},    t_{2k+1}}
    __shared__ float warp_sums[TILE / 32];

    int tid = threadIdx.x;

    // Stage the i-tile as packed pairs; half the threads load p, half load t.
    const float2* pred2 = reinterpret_cast<const float2*>(pred);
    const float2* targ2 = reinterpret_cast<const float2*>(target);
    if (tid < TILE / 2) {
        float2 v = pred2[bi * (TILE / 2) + tid];
        spp[tid] = packf2(10.0f * v.x, 10.0f * v.y);
    } else {
        int k = tid - TILE / 2;
        float2 v = targ2[bi * (TILE / 2) + k];
        stt[k] = packf2(v.x, v.y);
    }
    __syncthreads();

    // This thread owns one j column.
    int j = bj * TILE + tid;
    float pj = 10.0f * pred[j];
    float tj = target[j];
    ull npj2 = packf2(-pj, -pj);
    ull ntj2 = packf2(-tj, -tj);

    float acc0 = 0.0f, acc1 = 0.0f;

    if (bi != bj) {
        // Off-diagonal: all i < all j. 128 packed iterations = 256 pairs.
        #pragma unroll 8
        for (int k = 0; k < TILE / 2; k++) {
            unsigned th = tanh_h2(pair_args_h2(spp[k], stt[k], npj2, ntj2));
            __half2 h; *reinterpret_cast<unsigned*>(&h) = th;
            float2 f = __half22float2(h);
            acc0 += f.x;
            acc1 += f.y;
        }
    } else {
        // Diagonal tile: strict i < j only. Full pairs k cover i = 2k, 2k+1 < tid.
        int kmax = tid >> 1;   // pairs 0..kmax-1 fully below tid
        for (int k = 0; k < kmax; k++) {
            unsigned th = tanh_h2(pair_args_h2(spp[k], stt[k], npj2, ntj2));
            __half2 h; *reinterpret_cast<unsigned*>(&h) = th;
            float2 f = __half22float2(h);
            acc0 += f.x;
            acc1 += f.y;
        }
        if (tid & 1) {
            // One leftover element: i = tid - 1 (even), low half of pair kmax.
            float2 pv = *reinterpret_cast<float2*>(&spp[kmax]);
            float2 tv = *reinterpret_cast<float2*>(&stt[kmax]);
            float x = (pv.x - pj) * (tv.x - tj);
            acc0 += fast_tanhf(x);
        }
    }

    float acc = acc0 + acc1;

    // Warp reduction.
    #pragma unroll
    for (int off = 16; off > 0; off >>= 1)
        acc += __shfl_xor_sync(0xFFFFFFFFu, acc, off);

    int lane = tid & 31;
    int wid  = tid >> 5;
    if (lane == 0) warp_sums[wid] = acc;
    __syncthreads();

    if (tid == 0) {
        double s = 0.0;
        #pragma unroll
        for (int w = 0; w < TILE / 32; w++) s += (double)warp_sums[w];
        atomicAdd(&g_tau_sum, s);
        __threadfence();
        unsigned int old = atomicAdd(&g_count, 1u);
        if (old == (unsigned int)gridDim.x - 1u) {
            double total = *((volatile double*)&g_tau_sum);
            out[0] = (float)(total * inv_pairs);
            // Reset for the next graph replay.
            g_tau_sum = 0.0;
            g_count   = 0u;
            __threadfence();
        }
    }
}

extern "C" void kernel_launch(void* const* d_in, const int* in_sizes, int n_in,
                              void* d_out, int out_size) {
    const float* pred   = (const float*)d_in[0];
    const float* target = (const float*)d_in[1];
    float* out = (float*)d_out;

    int n  = in_sizes[0];              // 8192
    int nt = n / TILE;                 // 32
    int nblocks = nt * (nt + 1) / 2;   // 528

    double n_pairs   = 0.5 * (double)n * (double)(n - 1);
    double inv_pairs = 1.0 / n_pairs;

    ktau_kernel<<<nblocks, TILE>>>(pred, target, nt, out, inv_pairs);
}

// round 9
// speedup vs baseline: 1.0171x; 1.0171x over previous
#include <cuda_runtime.h>
#include <cuda_fp16.h>

// DifferentiableKendallTau: tau = sum_{i<j} tanh((p_j-p_i)*(t_j-t_i)/0.1) / (n*(n-1)/2)
// n = 8192. Single kernel, tiled all-pairs.
// Key trick: tanh.approx.f16x2 evaluates TWO pair agreements per MUFU slot,
// halving the MUFU roofline vs f32 tanh. Arguments stay fp32 (add/mul.rn.f32x2),
// only the tanh itself is fp16; accumulation is fp32 -> double.

#define TILE 256
typedef unsigned long long ull;

__device__ double       g_tau_sum;   // zero at module load; last block resets each launch
__device__ unsigned int g_count;

__device__ __forceinline__ float fast_tanhf(float x) {
    float y; asm("tanh.approx.f32 %0, %1;" : "=f"(y) : "f"(x)); return y;
}

__device__ __forceinline__ ull packf2(float x, float y) {
    float2 f = make_float2(x, y);
    return *reinterpret_cast<ull*>(&f);
}

// Two pair-arguments -> one f16x2 register.
// a = {10*p_i0, 10*p_i1}, b = {t_i0, t_i1}, npj2 = {-10*pj, -10*pj}, ntj2 = {-tj, -tj}
// x_k = (p_ik - pj)*10 * (t_ik - tj)  == 10*pd*td (sign-symmetric, matches reference)
__device__ __forceinline__ unsigned pair_args_h2(ull a, ull b, ull npj2, ull ntj2) {
    unsigned r;
    asm("{\n\t"
        ".reg .b64 pd, td, x2;\n\t"
        ".reg .f32 xlo, xhi;\n\t"
        "add.rn.f32x2 pd, %1, %2;\n\t"
        "add.rn.f32x2 td, %3, %4;\n\t"
        "mul.rn.f32x2 x2, pd, td;\n\t"
        "mov.b64 {xlo, xhi}, x2;\n\t"
        "cvt.rn.f16x2.f32 %0, xhi, xlo;\n\t"
        "}" : "=r"(r) : "l"(a), "l"(npj2), "l"(b), "l"(ntj2));
    return r;
}

__device__ __forceinline__ unsigned tanh_h2(unsigned x) {
    unsigned y; asm("tanh.approx.f16x2 %0, %1;" : "=r"(y) : "r"(x)); return y;
}

__global__ void __launch_bounds__(TILE)
ktau_kernel(const float* __restrict__ pred,
            const float* __restrict__ target,
            int nt, float* __restrict__ out, double inv_pairs) {
    // Decode linear block id -> (bi, bj), bi <= bj (upper-triangular tile pairs).
    int b = blockIdx.x;
    int bi = 0;
    int rem = b;
    while (rem >= nt - bi) { rem -= nt - bi; bi++; }
    int bj = bi + rem;

    __shared__ ull spp[TILE / 2];   // packed {10*p_{2k}, 10*p_{2k+1}}
    __shared__ ull stt[TILE / 2];   // packed {t_{2k},    t_{2k+1}}
    __shared__ float warp_sums[TILE / 32];

    int tid = threadIdx.x;

    // Stage the i-tile as packed pairs; half the threads load p, half load t.
    const float2* pred2 = reinterpret_cast<const float2*>(pred);
    const float2* targ2 = reinterpret_cast<const float2*>(target);
    if (tid < TILE / 2) {
        float2 v = pred2[bi * (TILE / 2) + tid];
        spp[tid] = packf2(10.0f * v.x, 10.0f * v.y);
    } else {
        int k = tid - TILE / 2;
        float2 v = targ2[bi * (TILE / 2) + k];
        stt[k] = packf2(v.x, v.y);
    }
    __syncthreads();

    // This thread owns one j column.
    int j = bj * TILE + tid;
    float pj = 10.0f * pred[j];
    float tj = target[j];
    ull npj2 = packf2(-pj, -pj);
    ull ntj2 = packf2(-tj, -tj);

    float acc0 = 0.0f, acc1 = 0.0f;

    if (bi != bj) {
        // Off-diagonal: all i < all j. 128 packed iterations = 256 pairs.
        #pragma unroll 8
        for (int k = 0; k < TILE / 2; k++) {
            unsigned th = tanh_h2(pair_args_h2(spp[k], stt[k], npj2, ntj2));
            __half2 h; *reinterpret_cast<unsigned*>(&h) = th;
            float2 f = __half22float2(h);
            acc0 += f.x;
            acc1 += f.y;
        }
    } else {
        // Diagonal tile: strict i < j only. Full pairs k cover i = 2k, 2k+1 < tid.
        int kmax = tid >> 1;   // pairs 0..kmax-1 fully below tid
        for (int k = 0; k < kmax; k++) {
            unsigned th = tanh_h2(pair_args_h2(spp[k], stt[k], npj2, ntj2));
            __half2 h; *reinterpret_cast<unsigned*>(&h) = th;
            float2 f = __half22float2(h);
            acc0 += f.x;
            acc1 += f.y;
        }
        if (tid & 1) {
            // One leftover element: i = tid - 1 (even), low half of pair kmax.
            float2 pv = *reinterpret_cast<float2*>(&spp[kmax]);
            float2 tv = *reinterpret_cast<float2*>(&stt[kmax]);
            float x = (pv.x - pj) * (tv.x - tj);
            acc0 += fast_tanhf(x);
        }
    }

    float acc = acc0 + acc1;

    // Warp reduction.
    #pragma unroll
    for (int off = 16; off > 0; off >>= 1)
        acc += __shfl_xor_sync(0xFFFFFFFFu, acc, off);

    int lane = tid & 31;
    int wid  = tid >> 5;
    if (lane == 0) warp_sums[wid] = acc;
    __syncthreads();

    if (tid == 0) {
        double s = 0.0;
        #pragma unroll
        for (int w = 0; w < TILE / 32; w++) s += (double)warp_sums[w];
        atomicAdd(&g_tau_sum, s);
        __threadfence();
        unsigned int old = atomicAdd(&g_count, 1u);
        if (old == (unsigned int)gridDim.x - 1u) {
            double total = *((volatile double*)&g_tau_sum);
            out[0] = (float)(total * inv_pairs);
            // Reset for the next graph replay.
            g_tau_sum = 0.0;
            g_count   = 0u;
            __threadfence();
        }
    }
}

extern "C" void kernel_launch(void* const* d_in, const int* in_sizes, int n_in,
                              void* d_out, int out_size) {
    const float* pred   = (const float*)d_in[0];
    const float* target = (const float*)d_in[1];
    float* out = (float*)d_out;

    int n  = in_sizes[0];              // 8192
    int nt = n / TILE;                 // 32
    int nblocks = nt * (nt + 1) / 2;   // 528

    double n_pairs   = 0.5 * (double)n * (double)(n - 1);
    double inv_pairs = 1.0 / n_pairs;

    ktau_kernel<<<nblocks, TILE>>>(pred, target, nt, out, inv_pairs);
}